// round 2
// baseline (speedup 1.0000x reference)
#include <cuda_runtime.h>
#include <cuda_fp16.h>
#include <cstdint>

#define C 64
#define D 512
#define TEMP_INV 10.0f
#define GLW 0.5f
#define NBLK_PRE 128

// ---------------- device globals (scratch; no allocation allowed) ----------------
__device__ float  g_sums[C * D];
__device__ int    g_hist_part[NBLK_PRE * C];   // per-block partial histograms (written, not accumulated)
__device__ float  g_loss[2];
__device__ int    g_done;                      // zero-init at load; reset by last block each run

// ---------------- K0: zero sums/loss + per-block label histogram ----------------
// grid = NBLK_PRE(128) x 256 threads. Block b hists labels[b*512 .. b*512+511].
__global__ void k_pre(const int* __restrict__ labels, int n) {
    __shared__ int h[C];
    int b = blockIdx.x, t = threadIdx.x;
    if (t < C) h[t] = 0;
    // zero my slice of g_sums (32768 / 128 = 256 per block)
    g_sums[b * 256 + t] = 0.f;
    if (b == 0 && t < 2) g_loss[t] = 0.f;
    __syncthreads();
    int per = n / NBLK_PRE;                 // 512
    for (int i = t; i < per; i += blockDim.x)
        atomicAdd(&h[labels[b * per + i]], 1);
    __syncthreads();
    if (t < C) g_hist_part[b * C + t] = h[t];
}

// ---------------- K1: centroid partial sums ----------------
// grid = 16 column-slices x 8 row-chunks = 128 blocks (single wave), 512 threads.
// Each warp owns a PRIVATE shared copy of sums[64][32] -> no shared atomics.
#define P1_THREADS 512
#define P1_COLS 32
#define P1_ROWCHUNKS 8
__global__ __launch_bounds__(P1_THREADS)
void k_csum(const float* __restrict__ S1, const int* __restrict__ labels, int n) {
    extern __shared__ float priv[];  // [16 warps][C][32] = 128 KB
    int tid = threadIdx.x, w = tid >> 5, lane = tid & 31;
    int colbase = (blockIdx.x & 15) * P1_COLS;
    int chunk = blockIdx.x >> 4;
    int rows_per_block = n / P1_ROWCHUNKS;           // 8192
    int rows_per_warp  = rows_per_block / 16;        // 512
    int r0 = chunk * rows_per_block + w * rows_per_warp;
    float* my = priv + w * (C * P1_COLS);

    for (int i = tid; i < 16 * C * P1_COLS; i += P1_THREADS) priv[i] = 0.f;
    __syncthreads();

    const float* base = S1 + colbase + lane;
    int r = r0;
    for (int i = 0; i < rows_per_warp; i += 4) {
        int4 l4 = *reinterpret_cast<const int4*>(labels + r);  // broadcast 16B
        float v0 = base[(size_t)(r + 0) * D];
        float v1 = base[(size_t)(r + 1) * D];
        float v2 = base[(size_t)(r + 2) * D];
        float v3 = base[(size_t)(r + 3) * D];
        my[l4.x * P1_COLS + lane] += v0;   // conflict-free: 32 consecutive words
        my[l4.y * P1_COLS + lane] += v1;
        my[l4.z * P1_COLS + lane] += v2;
        my[l4.w * P1_COLS + lane] += v3;
        r += 4;
    }
    __syncthreads();

    for (int idx = tid; idx < C * P1_COLS; idx += P1_THREADS) {
        int c = idx / P1_COLS, col = idx % P1_COLS;
        float s = 0.f;
#pragma unroll
        for (int ww = 0; ww < 16; ww++) s += priv[ww * (C * P1_COLS) + idx];
        atomicAdd(&g_sums[c * D + colbase + col], s);
    }
}

// ---------------- K2: fused staging + dual GEMM + weighted CE + finalize ----------------
__device__ __forceinline__ uint32_t f2h2(const float* p) {
    float2 f = *reinterpret_cast<const float2*>(p);
    __half2 h = __float22half2_rn(f);
    return *reinterpret_cast<uint32_t*>(&h);
}

__device__ __forceinline__ void mma16816(float* c,
                                         uint32_t a0, uint32_t a1, uint32_t a2, uint32_t a3,
                                         uint32_t b0, uint32_t b1) {
    asm volatile(
        "mma.sync.aligned.m16n8k16.row.col.f32.f16.f16.f32 "
        "{%0,%1,%2,%3}, {%4,%5,%6,%7}, {%8,%9}, {%0,%1,%2,%3};\n"
        : "+f"(c[0]), "+f"(c[1]), "+f"(c[2]), "+f"(c[3])
        : "r"(a0), "r"(a1), "r"(a2), "r"(a3), "r"(b0), "r"(b1));
}

#define P2_THREADS 256
#define P2_BLOCKS 296
#define CENT_STRIDE_H2 260   // (512+8)/2 half2 per class row -> conflict-free B loads
#define CENT_SMEM_BYTES (C * 520 * 2)

// One S-matrix pass: 16 rows x 64 classes, returns sum over this lane's rows of w*CE
// (quad-uniform; caller scales by 0.25).
__device__ __forceinline__ float gemm_ce_pass(const float* __restrict__ Ar1,
                                              const float* __restrict__ Ar2,
                                              const __half2* __restrict__ centh2,
                                              int lab0, int lab1, float w0, float w1,
                                              int g, int t) {
    float acc[8][4];
#pragma unroll
    for (int nt = 0; nt < 8; nt++)
#pragma unroll
        for (int j = 0; j < 4; j++) acc[nt][j] = 0.f;

#pragma unroll 4
    for (int kt = 0; kt < D / 16; kt++) {
        int k0 = kt * 16 + t * 2;
        uint32_t a0 = f2h2(Ar1 + k0);
        uint32_t a1 = f2h2(Ar2 + k0);
        uint32_t a2 = f2h2(Ar1 + k0 + 8);
        uint32_t a3 = f2h2(Ar2 + k0 + 8);
#pragma unroll
        for (int nt = 0; nt < 8; nt++) {
            const __half2* bp = centh2 + (nt * 8 + g) * CENT_STRIDE_H2 + (k0 >> 1);
            uint32_t b0 = *reinterpret_cast<const uint32_t*>(bp);
            uint32_t b1 = *reinterpret_cast<const uint32_t*>(bp + 4);
            mma16816(acc[nt], a0, a1, a2, a3, b0, b1);
        }
    }

    float out = 0.f;
#pragma unroll
    for (int j = 0; j < 2; j++) {
        int lab = j ? lab1 : lab0;
        float w = j ? w1 : w0;
        float mx = -1e30f;
#pragma unroll
        for (int nt = 0; nt < 8; nt++) {
            mx = fmaxf(mx, acc[nt][2 * j]);
            mx = fmaxf(mx, acc[nt][2 * j + 1]);
        }
        mx = fmaxf(mx, __shfl_xor_sync(0xffffffffu, mx, 1));
        mx = fmaxf(mx, __shfl_xor_sync(0xffffffffu, mx, 2));
        float s = 0.f;
#pragma unroll
        for (int nt = 0; nt < 8; nt++) {
            s += __expf(acc[nt][2 * j] - mx);
            s += __expf(acc[nt][2 * j + 1] - mx);
        }
        s += __shfl_xor_sync(0xffffffffu, s, 1);
        s += __shfl_xor_sync(0xffffffffu, s, 2);
        float lse = mx + __logf(s);
        int nt_l = lab >> 3;
        int t_l = (lab >> 1) & 3;
        float sel = 0.f;
#pragma unroll
        for (int nt = 0; nt < 8; nt++) {
            float v = (lab & 1) ? acc[nt][2 * j + 1] : acc[nt][2 * j];
            sel += ((nt == nt_l) && (t == t_l)) ? v : 0.f;
        }
        sel += __shfl_xor_sync(0xffffffffu, sel, 1);
        sel += __shfl_xor_sync(0xffffffffu, sel, 2);
        out += w * (lse - sel);   // quad-uniform
    }
    return out;
}

__global__ __launch_bounds__(P2_THREADS, 2)
void k_main(const float* __restrict__ S1, const float* __restrict__ S2,
            const int* __restrict__ labels, const float* __restrict__ sim,
            float* __restrict__ out, int n) {
    extern __shared__ __half cent_sh[];
    __shared__ float red[8][2];
    __shared__ float sc_sh[C];   // TEMP_INV / count[c]

    int tid = threadIdx.x;

    // counts from partial histograms (L2-hot)
    if (tid < C) {
        int cnt = 0;
#pragma unroll 8
        for (int p = 0; p < NBLK_PRE; p++) cnt += g_hist_part[p * C + tid];
        sc_sh[tid] = TEMP_INV / (float)cnt;
    }
    __syncthreads();

    // Stage centroids (scaled by 1/TEMP) into shared (half2, padded stride)
    {
        const float2* src = reinterpret_cast<const float2*>(g_sums);
        __half2* dst = reinterpret_cast<__half2*>(cent_sh);
        for (int i = tid; i < C * D / 2; i += P2_THREADS) {
            int c = i >> 8;          // 256 half2 per class
            float s = sc_sh[c];
            float2 v = src[i];
            dst[c * CENT_STRIDE_H2 + (i & 255)] = __floats2half2_rn(v.x * s, v.y * s);
        }
    }
    __syncthreads();

    const __half2* centh2 = reinterpret_cast<const __half2*>(cent_sh);
    int lane = tid & 31, wid = tid >> 5;
    int g = lane >> 2, t = lane & 3;
    int gwarp = blockIdx.x * (P2_THREADS / 32) + wid;
    int nwarps = gridDim.x * (P2_THREADS / 32);
    int ntiles = n >> 4;

    float lsum0 = 0.f, lsum1 = 0.f;

    for (int tile = gwarp; tile < ntiles; tile += nwarps) {
        int rb = tile << 4;
        int lab0 = labels[rb + g];
        int lab1 = labels[rb + 8 + g];
        float4 wv0 = *reinterpret_cast<const float4*>(sim + (size_t)(rb + g) * 16 + t * 4);
        float4 wv1 = *reinterpret_cast<const float4*>(sim + (size_t)(rb + 8 + g) * 16 + t * 4);
        float w0 = wv0.x + wv0.y + wv0.z + wv0.w;
        float w1 = wv1.x + wv1.y + wv1.z + wv1.w;
        w0 += __shfl_xor_sync(0xffffffffu, w0, 1);
        w0 += __shfl_xor_sync(0xffffffffu, w0, 2);
        w1 += __shfl_xor_sync(0xffffffffu, w1, 1);
        w1 += __shfl_xor_sync(0xffffffffu, w1, 2);
        w0 *= (1.f / 16.f);
        w1 *= (1.f / 16.f);

        const float* a1r1 = S1 + (size_t)(rb + g) * D;
        const float* a2r1 = S2 + (size_t)(rb + g) * D;
        lsum0 += gemm_ce_pass(a1r1, a1r1 + 8 * D, centh2, lab0, lab1, w0, w1, g, t);
        lsum1 += gemm_ce_pass(a2r1, a2r1 + 8 * D, centh2, lab0, lab1, w0, w1, g, t);
    }

    // each CE was accumulated on all 4 quad lanes -> scale by 1/4
    lsum0 *= 0.25f;
    lsum1 *= 0.25f;
#pragma unroll
    for (int off = 16; off > 0; off >>= 1) {
        lsum0 += __shfl_down_sync(0xffffffffu, lsum0, off);
        lsum1 += __shfl_down_sync(0xffffffffu, lsum1, off);
    }
    if (lane == 0) { red[wid][0] = lsum0; red[wid][1] = lsum1; }
    __syncthreads();
    if (tid == 0) {
        float s0 = 0.f, s1 = 0.f;
#pragma unroll
        for (int wq = 0; wq < P2_THREADS / 32; wq++) { s0 += red[wq][0]; s1 += red[wq][1]; }
        atomicAdd(&g_loss[0], s0);
        atomicAdd(&g_loss[1], s1);
        __threadfence();
        int ticket = atomicAdd(&g_done, 1);
        if (ticket == gridDim.x - 1) {
            float L = g_loss[0] / (float)n;
            float G = g_loss[1] / (float)n;
            out[0] = 0.5f * ((1.f - GLW) * L + GLW * G);
            atomicExch(&g_done, 0);   // reset for next graph replay
        }
    }
}

// ---------------- launch ----------------
extern "C" void kernel_launch(void* const* d_in, const int* in_sizes, int n_in,
                              void* d_out, int out_size) {
    const float* S1 = (const float*)d_in[0];
    const float* S2 = (const float*)d_in[1];
    const int* seg = (const int*)d_in[2];
    const float* sim = (const float*)d_in[3];
    int n = in_sizes[2];  // N = 65536

    cudaFuncSetAttribute(k_csum, cudaFuncAttributeMaxDynamicSharedMemorySize,
                         16 * C * P1_COLS * (int)sizeof(float));
    cudaFuncSetAttribute(k_main, cudaFuncAttributeMaxDynamicSharedMemorySize,
                         CENT_SMEM_BYTES);

    k_pre<<<NBLK_PRE, 256>>>(seg, n);
    k_csum<<<16 * P1_ROWCHUNKS, P1_THREADS, 16 * C * P1_COLS * sizeof(float)>>>(S1, seg, n);
    k_main<<<P2_BLOCKS, P2_THREADS, CENT_SMEM_BYTES>>>(S1, S2, seg, sim, (float*)d_out, n);
}

// round 4
// speedup vs baseline: 1.0483x; 1.0483x over previous
#include <cuda_runtime.h>
#include <cuda_fp16.h>
#include <cstdint>

#define C 64
#define D 512
#define TEMP_INV 10.0f
#define GLW 0.5f
#define NBLK_PRE 128

// ---------------- device globals (scratch; no allocation allowed) ----------------
__device__ float  g_sums[C * D];
__device__ int    g_hist_part[NBLK_PRE * C];   // per-block partial histograms
__device__ float  g_loss[2];
__device__ int    g_done;                      // zero-init at load; reset by last block each run

// ---------------- K0: zero sums/loss + per-block label histogram ----------------
__global__ void k_pre(const int* __restrict__ labels, int n) {
    __shared__ int h[C];
    int b = blockIdx.x, t = threadIdx.x;
    if (t < C) h[t] = 0;
    g_sums[b * 256 + t] = 0.f;                 // 128 blocks x 256 = 32768
    if (b == 0 && t < 2) g_loss[t] = 0.f;
    __syncthreads();
    int per = n / NBLK_PRE;                    // 512
    for (int i = t; i < per; i += blockDim.x)
        atomicAdd(&h[labels[b * per + i]], 1);
    __syncthreads();
    if (t < C) g_hist_part[b * C + t] = h[t];
}

// ---------------- K1: centroid partial sums (R1 proven config: 512 blocks) ----------------
#define P1_THREADS 512
#define P1_COLS 32
#define P1_ROWCHUNKS 32
__global__ __launch_bounds__(P1_THREADS)
void k_csum(const float* __restrict__ S1, const int* __restrict__ labels, int n) {
    extern __shared__ float priv[];  // [16 warps][C][32] = 128 KB
    int tid = threadIdx.x, w = tid >> 5, lane = tid & 31;
    int colbase = (blockIdx.x & 15) * P1_COLS;
    int chunk = blockIdx.x >> 4;
    int rows_per_block = n / P1_ROWCHUNKS;           // 2048
    int rows_per_warp  = rows_per_block / 16;        // 128
    int r0 = chunk * rows_per_block + w * rows_per_warp;
    float* my = priv + w * (C * P1_COLS);

    for (int i = tid; i < 16 * C * P1_COLS; i += P1_THREADS) priv[i] = 0.f;
    __syncthreads();

    const float* base = S1 + colbase + lane;
    int r = r0;
    for (int i = 0; i < rows_per_warp; i += 4) {
        int4 l4 = *reinterpret_cast<const int4*>(labels + r);  // broadcast 16B
        float v0 = base[(size_t)(r + 0) * D];
        float v1 = base[(size_t)(r + 1) * D];
        float v2 = base[(size_t)(r + 2) * D];
        float v3 = base[(size_t)(r + 3) * D];
        my[l4.x * P1_COLS + lane] += v0;   // conflict-free: 32 consecutive words
        my[l4.y * P1_COLS + lane] += v1;
        my[l4.z * P1_COLS + lane] += v2;
        my[l4.w * P1_COLS + lane] += v3;
        r += 4;
    }
    __syncthreads();

    for (int idx = tid; idx < C * P1_COLS; idx += P1_THREADS) {
        int c = idx / P1_COLS, col = idx % P1_COLS;
        float s = 0.f;
#pragma unroll
        for (int ww = 0; ww < 16; ww++) s += priv[ww * (C * P1_COLS) + idx];
        atomicAdd(&g_sums[c * D + colbase + col], s);
    }
}

// ---------------- K2: fused staging + INTERLEAVED dual GEMM + weighted CE + finalize ----------------
__device__ __forceinline__ uint32_t f2h2(const float* p) {
    float2 f = *reinterpret_cast<const float2*>(p);
    __half2 h = __float22half2_rn(f);
    return *reinterpret_cast<uint32_t*>(&h);
}

__device__ __forceinline__ void mma16816(float* c,
                                         uint32_t a0, uint32_t a1, uint32_t a2, uint32_t a3,
                                         uint32_t b0, uint32_t b1) {
    asm volatile(
        "mma.sync.aligned.m16n8k16.row.col.f32.f16.f16.f32 "
        "{%0,%1,%2,%3}, {%4,%5,%6,%7}, {%8,%9}, {%0,%1,%2,%3};\n"
        : "+f"(c[0]), "+f"(c[1]), "+f"(c[2]), "+f"(c[3])
        : "r"(a0), "r"(a1), "r"(a2), "r"(a3), "r"(b0), "r"(b1));
}

#define P2_THREADS 256
#define P2_BLOCKS 256
#define CENT_STRIDE_H2 260   // (512+8)/2 half2 per class row -> conflict-free B loads
#define CENT_SMEM_BYTES (C * 520 * 2)

__global__ __launch_bounds__(P2_THREADS, 2)
void k_main(const float* __restrict__ S1, const float* __restrict__ S2,
            const int* __restrict__ labels, const float* __restrict__ sim,
            float* __restrict__ out, int n) {
    extern __shared__ __half cent_sh[];
    __shared__ float red[8][2];
    __shared__ float sc_sh[C];   // TEMP_INV / count[c]

    int tid = threadIdx.x;

    // counts from partial histograms (L2-hot)
    if (tid < C) {
        int cnt = 0;
#pragma unroll 8
        for (int p = 0; p < NBLK_PRE; p++) cnt += g_hist_part[p * C + tid];
        sc_sh[tid] = TEMP_INV / (float)cnt;
    }
    __syncthreads();

    // Stage centroids (scaled by 1/TEMP) into shared (half2, padded stride)
    {
        const float2* src = reinterpret_cast<const float2*>(g_sums);
        __half2* dst = reinterpret_cast<__half2*>(cent_sh);
        for (int i = tid; i < C * D / 2; i += P2_THREADS) {
            int c = i >> 8;          // 256 half2 per class
            float s = sc_sh[c];
            float2 v = src[i];
            dst[c * CENT_STRIDE_H2 + (i & 255)] = __floats2half2_rn(v.x * s, v.y * s);
        }
    }
    __syncthreads();

    const __half2* centh2 = reinterpret_cast<const __half2*>(cent_sh);
    int lane = tid & 31, wid = tid >> 5;
    int g = lane >> 2, t = lane & 3;
    int gwarp = blockIdx.x * (P2_THREADS / 32) + wid;
    int nwarps = gridDim.x * (P2_THREADS / 32);
    int ntiles = n >> 4;

    float lsum0 = 0.f, lsum1 = 0.f;

    for (int tile = gwarp; tile < ntiles; tile += nwarps) {
        int rb = tile << 4;
        const float* a1r1 = S1 + (size_t)(rb + g) * D;
        const float* a1r2 = a1r1 + 8 * D;
        const float* a2r1 = S2 + (size_t)(rb + g) * D;
        const float* a2r2 = a2r1 + 8 * D;

        float acc[2][8][4];
#pragma unroll
        for (int m = 0; m < 2; m++)
#pragma unroll
            for (int nt = 0; nt < 8; nt++)
#pragma unroll
                for (int j = 0; j < 4; j++) acc[m][nt][j] = 0.f;

#pragma unroll 4
        for (int kt = 0; kt < D / 16; kt++) {
            int k0 = kt * 16 + t * 2;
            uint32_t a0m0 = f2h2(a1r1 + k0);
            uint32_t a1m0 = f2h2(a1r2 + k0);
            uint32_t a2m0 = f2h2(a1r1 + k0 + 8);
            uint32_t a3m0 = f2h2(a1r2 + k0 + 8);
            uint32_t a0m1 = f2h2(a2r1 + k0);
            uint32_t a1m1 = f2h2(a2r2 + k0);
            uint32_t a2m1 = f2h2(a2r1 + k0 + 8);
            uint32_t a3m1 = f2h2(a2r2 + k0 + 8);
#pragma unroll
            for (int nt = 0; nt < 8; nt++) {
                const __half2* bp = centh2 + (nt * 8 + g) * CENT_STRIDE_H2 + (k0 >> 1);
                uint32_t b0 = *reinterpret_cast<const uint32_t*>(bp);
                uint32_t b1 = *reinterpret_cast<const uint32_t*>(bp + 4);
                mma16816(acc[0][nt], a0m0, a1m0, a2m0, a3m0, b0, b1);
                mma16816(acc[1][nt], a0m1, a1m1, a2m1, a3m1, b0, b1);
            }
        }

        int lab0 = labels[rb + g];
        int lab1 = labels[rb + 8 + g];

        float4 wv0 = *reinterpret_cast<const float4*>(sim + (size_t)(rb + g) * 16 + t * 4);
        float4 wv1 = *reinterpret_cast<const float4*>(sim + (size_t)(rb + 8 + g) * 16 + t * 4);
        float w0 = wv0.x + wv0.y + wv0.z + wv0.w;
        float w1 = wv1.x + wv1.y + wv1.z + wv1.w;
        w0 += __shfl_xor_sync(0xffffffffu, w0, 1);
        w0 += __shfl_xor_sync(0xffffffffu, w0, 2);
        w1 += __shfl_xor_sync(0xffffffffu, w1, 1);
        w1 += __shfl_xor_sync(0xffffffffu, w1, 2);
        w0 *= (1.f / 16.f);
        w1 *= (1.f / 16.f);

#pragma unroll
        for (int m = 0; m < 2; m++) {
#pragma unroll
            for (int j = 0; j < 2; j++) {
                int lab = j ? lab1 : lab0;
                float w = j ? w1 : w0;
                float mx = -1e30f;
#pragma unroll
                for (int nt = 0; nt < 8; nt++) {
                    mx = fmaxf(mx, acc[m][nt][2 * j]);
                    mx = fmaxf(mx, acc[m][nt][2 * j + 1]);
                }
                mx = fmaxf(mx, __shfl_xor_sync(0xffffffffu, mx, 1));
                mx = fmaxf(mx, __shfl_xor_sync(0xffffffffu, mx, 2));
                float s = 0.f;
#pragma unroll
                for (int nt = 0; nt < 8; nt++) {
                    s += __expf(acc[m][nt][2 * j] - mx);
                    s += __expf(acc[m][nt][2 * j + 1] - mx);
                }
                s += __shfl_xor_sync(0xffffffffu, s, 1);
                s += __shfl_xor_sync(0xffffffffu, s, 2);
                float lse = mx + __logf(s);
                int nt_l = lab >> 3;
                int t_l = (lab >> 1) & 3;
                float sel = 0.f;
#pragma unroll
                for (int nt = 0; nt < 8; nt++) {
                    float v = (lab & 1) ? acc[m][nt][2 * j + 1] : acc[m][nt][2 * j];
                    sel += ((nt == nt_l) && (t == t_l)) ? v : 0.f;
                }
                sel += __shfl_xor_sync(0xffffffffu, sel, 1);
                sel += __shfl_xor_sync(0xffffffffu, sel, 2);
                float ce = (lse - sel) * w;   // quad-uniform
                if (m == 0) lsum0 += ce;
                else        lsum1 += ce;
            }
        }
    }

    // CE accumulated on all 4 quad lanes -> scale by 1/4
    lsum0 *= 0.25f;
    lsum1 *= 0.25f;
#pragma unroll
    for (int off = 16; off > 0; off >>= 1) {
        lsum0 += __shfl_down_sync(0xffffffffu, lsum0, off);
        lsum1 += __shfl_down_sync(0xffffffffu, lsum1, off);
    }
    if (lane == 0) { red[wid][0] = lsum0; red[wid][1] = lsum1; }
    __syncthreads();
    if (tid == 0) {
        float s0 = 0.f, s1 = 0.f;
#pragma unroll
        for (int wq = 0; wq < P2_THREADS / 32; wq++) { s0 += red[wq][0]; s1 += red[wq][1]; }
        atomicAdd(&g_loss[0], s0);
        atomicAdd(&g_loss[1], s1);
        __threadfence();
        int ticket = atomicAdd(&g_done, 1);
        if (ticket == gridDim.x - 1) {
            float L = g_loss[0] / (float)n;
            float G = g_loss[1] / (float)n;
            out[0] = 0.5f * ((1.f - GLW) * L + GLW * G);
            atomicExch(&g_done, 0);   // reset for next graph replay
        }
    }
}

// ---------------- launch ----------------
extern "C" void kernel_launch(void* const* d_in, const int* in_sizes, int n_in,
                              void* d_out, int out_size) {
    const float* S1 = (const float*)d_in[0];
    const float* S2 = (const float*)d_in[1];
    const int* seg = (const int*)d_in[2];
    const float* sim = (const float*)d_in[3];
    int n = in_sizes[2];  // N = 65536

    cudaFuncSetAttribute(k_csum, cudaFuncAttributeMaxDynamicSharedMemorySize,
                         16 * C * P1_COLS * (int)sizeof(float));
    cudaFuncSetAttribute(k_main, cudaFuncAttributeMaxDynamicSharedMemorySize,
                         CENT_SMEM_BYTES);

    k_pre<<<NBLK_PRE, 256>>>(seg, n);
    k_csum<<<16 * P1_ROWCHUNKS, P1_THREADS, 16 * C * P1_COLS * sizeof(float)>>>(S1, seg, n);
    k_main<<<P2_BLOCKS, P2_THREADS, CENT_SMEM_BYTES>>>(S1, S2, seg, sim, (float*)d_out, n);
}

// round 6
// speedup vs baseline: 1.1094x; 1.0584x over previous
#include <cuda_runtime.h>
#include <cuda_fp16.h>
#include <cstdint>

#define C 64
#define D 512
#define TEMP_INV 10.0f
#define GLW 0.5f
#define NBLK_PRE 128

// ---------------- device globals (scratch; no allocation allowed) ----------------
__device__ float  g_sums[C * D];
__device__ __half g_cent[C * D];               // fp16 centroids, TEMP/count folded
__device__ int    g_hist_part[NBLK_PRE * C];   // per-block partial histograms
__device__ float  g_loss[2];
__device__ int    g_done;                      // zero-init at load; reset by last block each run

// ---------------- K0: zero sums/loss + per-block label histogram ----------------
__global__ void k_pre(const int* __restrict__ labels, int n) {
    __shared__ int h[C];
    int b = blockIdx.x, t = threadIdx.x;
    if (t < C) h[t] = 0;
    g_sums[b * 256 + t] = 0.f;                 // 128 blocks x 256 = 32768
    if (b == 0 && t < 2) g_loss[t] = 0.f;
    __syncthreads();
    int per = n / NBLK_PRE;                    // 512
    for (int i = t; i < per; i += blockDim.x)
        atomicAdd(&h[labels[b * per + i]], 1);
    __syncthreads();
    if (t < C) g_hist_part[b * C + t] = h[t];
}

// ---------------- K1: centroid partial sums (512 blocks, proven config) ----------------
#define P1_THREADS 512
#define P1_COLS 32
#define P1_ROWCHUNKS 32
__global__ __launch_bounds__(P1_THREADS)
void k_csum(const float* __restrict__ S1, const int* __restrict__ labels, int n) {
    extern __shared__ float priv[];  // [16 warps][C][32] = 128 KB
    int tid = threadIdx.x, w = tid >> 5, lane = tid & 31;
    int colbase = (blockIdx.x & 15) * P1_COLS;
    int chunk = blockIdx.x >> 4;
    int rows_per_block = n / P1_ROWCHUNKS;           // 2048
    int rows_per_warp  = rows_per_block / 16;        // 128
    int r0 = chunk * rows_per_block + w * rows_per_warp;
    float* my = priv + w * (C * P1_COLS);

    for (int i = tid; i < 16 * C * P1_COLS; i += P1_THREADS) priv[i] = 0.f;
    __syncthreads();

    const float* base = S1 + colbase + lane;
    int r = r0;
    for (int i = 0; i < rows_per_warp; i += 4) {
        int4 l4 = *reinterpret_cast<const int4*>(labels + r);  // broadcast 16B
        float v0 = base[(size_t)(r + 0) * D];
        float v1 = base[(size_t)(r + 1) * D];
        float v2 = base[(size_t)(r + 2) * D];
        float v3 = base[(size_t)(r + 3) * D];
        my[l4.x * P1_COLS + lane] += v0;   // conflict-free: 32 consecutive words
        my[l4.y * P1_COLS + lane] += v1;
        my[l4.z * P1_COLS + lane] += v2;
        my[l4.w * P1_COLS + lane] += v3;
        r += 4;
    }
    __syncthreads();

    for (int idx = tid; idx < C * P1_COLS; idx += P1_THREADS) {
        int c = idx / P1_COLS, col = idx % P1_COLS;
        float s = 0.f;
#pragma unroll
        for (int ww = 0; ww < 16; ww++) s += priv[ww * (C * P1_COLS) + idx];
        atomicAdd(&g_sums[c * D + colbase + col], s);
    }
}

// ---------------- K2: counts + fp32->fp16 centroid conversion (one block per class) ----
__global__ void k_conv() {
    __shared__ int part[NBLK_PRE];
    __shared__ float sc_sh;
    int c = blockIdx.x, t = threadIdx.x;   // 64 blocks x 128 threads
    part[t] = g_hist_part[t * C + c];
    __syncthreads();
    if (t < 64) part[t] += part[t + 64];
    __syncthreads();
    if (t < 32) {
        int v = part[t] + part[t + 32];
#pragma unroll
        for (int off = 16; off > 0; off >>= 1) v += __shfl_down_sync(0xffffffffu, v, off);
        if (t == 0) sc_sh = TEMP_INV / (float)v;
    }
    __syncthreads();
    float sc = sc_sh;
    // 512 floats per class = 128 float4; one per thread
    float4 v = reinterpret_cast<const float4*>(g_sums + c * D)[t];
    __half2* dst = reinterpret_cast<__half2*>(g_cent + c * D);
    dst[2 * t]     = __floats2half2_rn(v.x * sc, v.y * sc);
    dst[2 * t + 1] = __floats2half2_rn(v.z * sc, v.w * sc);
}

// ---------------- K3: staging + interleaved dual GEMM + weighted CE + finalize -------
__device__ __forceinline__ uint32_t f2h2(const float* p) {
    float2 f = *reinterpret_cast<const float2*>(p);
    __half2 h = __float22half2_rn(f);
    return *reinterpret_cast<uint32_t*>(&h);
}

__device__ __forceinline__ void mma16816(float* c,
                                         uint32_t a0, uint32_t a1, uint32_t a2, uint32_t a3,
                                         uint32_t b0, uint32_t b1) {
    asm volatile(
        "mma.sync.aligned.m16n8k16.row.col.f32.f16.f16.f32 "
        "{%0,%1,%2,%3}, {%4,%5,%6,%7}, {%8,%9}, {%0,%1,%2,%3};\n"
        : "+f"(c[0]), "+f"(c[1]), "+f"(c[2]), "+f"(c[3])
        : "r"(a0), "r"(a1), "r"(a2), "r"(a3), "r"(b0), "r"(b1));
}

#define P2_THREADS 256
#define P2_BLOCKS 296
#define CENT_STRIDE_H2 260   // (512+8)/2 half2 per class row -> conflict-free B loads
#define CENT_SMEM_BYTES (C * 520 * 2)

__global__ __launch_bounds__(P2_THREADS, 2)
void k_main(const float* __restrict__ S1, const float* __restrict__ S2,
            const int* __restrict__ labels, const float* __restrict__ sim,
            float* __restrict__ out, int n) {
    extern __shared__ __half cent_sh[];
    __shared__ float red[8][2];

    int tid = threadIdx.x;

    // Stage fp16 centroids into padded shared: 4096 uint4 (8 halfs each)
    {
        const uint4* src = reinterpret_cast<const uint4*>(g_cent);
        for (int i = tid; i < C * D / 8; i += P2_THREADS) {
            int c = i >> 6;                 // 64 uint4 per class row
            int x8 = i & 63;                // which 8-half chunk
            *reinterpret_cast<uint4*>(cent_sh + c * 520 + x8 * 8) = src[i];
        }
    }
    __syncthreads();

    const __half2* centh2 = reinterpret_cast<const __half2*>(cent_sh);
    int lane = tid & 31, wid = tid >> 5;
    int g = lane >> 2, t = lane & 3;
    int gwarp = blockIdx.x * (P2_THREADS / 32) + wid;
    int nwarps = gridDim.x * (P2_THREADS / 32);
    int ntiles = n >> 4;

    float lsum0 = 0.f, lsum1 = 0.f;

    for (int tile = gwarp; tile < ntiles; tile += nwarps) {
        int rb = tile << 4;

        // Hoisted: labels + sim weights load BEFORE the MMA loop (overlap latency)
        int lab0 = labels[rb + g];
        int lab1 = labels[rb + 8 + g];
        float4 wv0 = *reinterpret_cast<const float4*>(sim + (size_t)(rb + g) * 16 + t * 4);
        float4 wv1 = *reinterpret_cast<const float4*>(sim + (size_t)(rb + 8 + g) * 16 + t * 4);

        const float* a1r1 = S1 + (size_t)(rb + g) * D;
        const float* a1r2 = a1r1 + 8 * D;
        const float* a2r1 = S2 + (size_t)(rb + g) * D;
        const float* a2r2 = a2r1 + 8 * D;

        float acc[2][8][4];
#pragma unroll
        for (int m = 0; m < 2; m++)
#pragma unroll
            for (int nt = 0; nt < 8; nt++)
#pragma unroll
                for (int j = 0; j < 4; j++) acc[m][nt][j] = 0.f;

#pragma unroll 8
        for (int kt = 0; kt < D / 16; kt++) {
            int k0 = kt * 16 + t * 2;
            uint32_t a0m0 = f2h2(a1r1 + k0);
            uint32_t a1m0 = f2h2(a1r2 + k0);
            uint32_t a2m0 = f2h2(a1r1 + k0 + 8);
            uint32_t a3m0 = f2h2(a1r2 + k0 + 8);
            uint32_t a0m1 = f2h2(a2r1 + k0);
            uint32_t a1m1 = f2h2(a2r2 + k0);
            uint32_t a2m1 = f2h2(a2r1 + k0 + 8);
            uint32_t a3m1 = f2h2(a2r2 + k0 + 8);
#pragma unroll
            for (int nt = 0; nt < 8; nt++) {
                const __half2* bp = centh2 + (nt * 8 + g) * CENT_STRIDE_H2 + (k0 >> 1);
                uint32_t b0 = *reinterpret_cast<const uint32_t*>(bp);
                uint32_t b1 = *reinterpret_cast<const uint32_t*>(bp + 4);
                mma16816(acc[0][nt], a0m0, a1m0, a2m0, a3m0, b0, b1);
                mma16816(acc[1][nt], a0m1, a1m1, a2m1, a3m1, b0, b1);
            }
        }

        float w0 = wv0.x + wv0.y + wv0.z + wv0.w;
        float w1 = wv1.x + wv1.y + wv1.z + wv1.w;
        w0 += __shfl_xor_sync(0xffffffffu, w0, 1);
        w0 += __shfl_xor_sync(0xffffffffu, w0, 2);
        w1 += __shfl_xor_sync(0xffffffffu, w1, 1);
        w1 += __shfl_xor_sync(0xffffffffu, w1, 2);
        w0 *= (1.f / 16.f);
        w1 *= (1.f / 16.f);

#pragma unroll
        for (int m = 0; m < 2; m++) {
#pragma unroll
            for (int j = 0; j < 2; j++) {
                int lab = j ? lab1 : lab0;
                float w = j ? w1 : w0;
                float mx = -1e30f;
#pragma unroll
                for (int nt = 0; nt < 8; nt++) {
                    mx = fmaxf(mx, acc[m][nt][2 * j]);
                    mx = fmaxf(mx, acc[m][nt][2 * j + 1]);
                }
                mx = fmaxf(mx, __shfl_xor_sync(0xffffffffu, mx, 1));
                mx = fmaxf(mx, __shfl_xor_sync(0xffffffffu, mx, 2));
                float s = 0.f;
#pragma unroll
                for (int nt = 0; nt < 8; nt++) {
                    s += __expf(acc[m][nt][2 * j] - mx);
                    s += __expf(acc[m][nt][2 * j + 1] - mx);
                }
                s += __shfl_xor_sync(0xffffffffu, s, 1);
                s += __shfl_xor_sync(0xffffffffu, s, 2);
                float lse = mx + __logf(s);
                int nt_l = lab >> 3;
                int t_l = (lab >> 1) & 3;
                float sel = 0.f;
#pragma unroll
                for (int nt = 0; nt < 8; nt++) {
                    float v = (lab & 1) ? acc[m][nt][2 * j + 1] : acc[m][nt][2 * j];
                    sel += ((nt == nt_l) && (t == t_l)) ? v : 0.f;
                }
                sel += __shfl_xor_sync(0xffffffffu, sel, 1);
                sel += __shfl_xor_sync(0xffffffffu, sel, 2);
                float ce = (lse - sel) * w;   // quad-uniform
                if (m == 0) lsum0 += ce;
                else        lsum1 += ce;
            }
        }
    }

    // CE accumulated on all 4 quad lanes -> scale by 1/4
    lsum0 *= 0.25f;
    lsum1 *= 0.25f;
#pragma unroll
    for (int off = 16; off > 0; off >>= 1) {
        lsum0 += __shfl_down_sync(0xffffffffu, lsum0, off);
        lsum1 += __shfl_down_sync(0xffffffffu, lsum1, off);
    }
    if (lane == 0) { red[wid][0] = lsum0; red[wid][1] = lsum1; }
    __syncthreads();
    if (tid == 0) {
        float s0 = 0.f, s1 = 0.f;
#pragma unroll
        for (int wq = 0; wq < P2_THREADS / 32; wq++) { s0 += red[wq][0]; s1 += red[wq][1]; }
        atomicAdd(&g_loss[0], s0);
        atomicAdd(&g_loss[1], s1);
        __threadfence();
        int ticket = atomicAdd(&g_done, 1);
        if (ticket == gridDim.x - 1) {
            float L = g_loss[0] / (float)n;
            float G = g_loss[1] / (float)n;
            out[0] = 0.5f * ((1.f - GLW) * L + GLW * G);
            atomicExch(&g_done, 0);   // reset for next graph replay
        }
    }
}

// ---------------- launch ----------------
extern "C" void kernel_launch(void* const* d_in, const int* in_sizes, int n_in,
                              void* d_out, int out_size) {
    const float* S1 = (const float*)d_in[0];
    const float* S2 = (const float*)d_in[1];
    const int* seg = (const int*)d_in[2];
    const float* sim = (const float*)d_in[3];
    int n = in_sizes[2];  // N = 65536

    cudaFuncSetAttribute(k_csum, cudaFuncAttributeMaxDynamicSharedMemorySize,
                         16 * C * P1_COLS * (int)sizeof(float));
    cudaFuncSetAttribute(k_main, cudaFuncAttributeMaxDynamicSharedMemorySize,
                         CENT_SMEM_BYTES);

    k_pre<<<NBLK_PRE, 256>>>(seg, n);
    k_csum<<<16 * P1_ROWCHUNKS, P1_THREADS, 16 * C * P1_COLS * sizeof(float)>>>(S1, seg, n);
    k_conv<<<C, NBLK_PRE>>>();
    k_main<<<P2_BLOCKS, P2_THREADS, CENT_SMEM_BYTES>>>(S1, S2, seg, sim, (float*)d_out, n);
}

// round 7
// speedup vs baseline: 1.1732x; 1.0575x over previous
#include <cuda_runtime.h>
#include <cuda_fp16.h>
#include <cstdint>

#define C 64
#define D 512
#define TEMP_INV 10.0f
#define GLW 0.5f
#define NCHUNK 32

// ---------------- device globals (scratch; no allocation allowed) ----------------
__device__ float  g_part[NCHUNK * C * D];      // per-chunk centroid partials (overwritten, no zeroing)
__device__ int    g_hist_part[NCHUNK * C];     // per-chunk label histograms
__device__ __half g_cent[C * D];               // fp16 centroids, TEMP/count folded
__device__ float  g_loss[2];
__device__ int    g_done;                      // zero-init at load; reset by last block each run

// ---------------- K0: centroid partials + (slice-0) histogram ----------------
// grid = 16 col-slices x 32 row-chunks = 512 blocks, 512 threads, 128 KB smem.
// Each warp owns a PRIVATE shared copy of sums[64][32] -> no shared atomics on values.
// 8-row unrolled: all LDGs front-batched before smem RMWs (MLP_p1 ~ 10).
#define P1_THREADS 512
#define P1_COLS 32
__global__ __launch_bounds__(P1_THREADS)
void k_csum(const float* __restrict__ S1, const int* __restrict__ labels, int n) {
    extern __shared__ float priv[];  // [16 warps][C][32] = 128 KB
    __shared__ int hist[C];
    int tid = threadIdx.x, w = tid >> 5, lane = tid & 31;
    int slice = blockIdx.x & 15;
    int chunk = blockIdx.x >> 4;
    int colbase = slice * P1_COLS;
    bool do_hist = (slice == 0);
    int rows_per_block = n / NCHUNK;                 // 2048
    int rows_per_warp  = rows_per_block / 16;        // 128
    int r0 = chunk * rows_per_block + w * rows_per_warp;
    float* my = priv + w * (C * P1_COLS);

    if (do_hist && tid < C) hist[tid] = 0;
    for (int i = tid; i < 16 * C * P1_COLS; i += P1_THREADS) priv[i] = 0.f;
    __syncthreads();

    const float* base = S1 + colbase + lane;
    int r = r0;
    for (int i = 0; i < rows_per_warp; i += 8) {
        // ---- front-batched loads (independent; high MLP) ----
        int4 la = *reinterpret_cast<const int4*>(labels + r);
        int4 lb = *reinterpret_cast<const int4*>(labels + r + 4);
        const float* p = base + (size_t)r * D;
        float v0 = p[0 * D];
        float v1 = p[1 * D];
        float v2 = p[2 * D];
        float v3 = p[3 * D];
        float v4 = p[4 * D];
        float v5 = p[5 * D];
        float v6 = p[6 * D];
        float v7 = p[7 * D];
        // ---- consume ----
        if (do_hist && lane == 0) {
            atomicAdd(&hist[la.x], 1); atomicAdd(&hist[la.y], 1);
            atomicAdd(&hist[la.z], 1); atomicAdd(&hist[la.w], 1);
            atomicAdd(&hist[lb.x], 1); atomicAdd(&hist[lb.y], 1);
            atomicAdd(&hist[lb.z], 1); atomicAdd(&hist[lb.w], 1);
        }
        my[la.x * P1_COLS + lane] += v0;   // conflict-free: 32 consecutive words
        my[la.y * P1_COLS + lane] += v1;
        my[la.z * P1_COLS + lane] += v2;
        my[la.w * P1_COLS + lane] += v3;
        my[lb.x * P1_COLS + lane] += v4;
        my[lb.y * P1_COLS + lane] += v5;
        my[lb.z * P1_COLS + lane] += v6;
        my[lb.w * P1_COLS + lane] += v7;
        r += 8;
    }
    __syncthreads();

    // reduce 16 warp copies -> plain coalesced STORE (no atomics, no pre-zero needed)
    float* dst = g_part + (size_t)chunk * (C * D);
    for (int idx = tid; idx < C * P1_COLS; idx += P1_THREADS) {
        int c = idx >> 5, col = idx & 31;
        float s = 0.f;
#pragma unroll
        for (int ww = 0; ww < 16; ww++) s += priv[ww * (C * P1_COLS) + idx];
        dst[c * D + colbase + col] = s;
    }
    if (do_hist && tid < C) g_hist_part[chunk * C + tid] = hist[tid];
}

// ---------------- K1: reduce partials + fp32->fp16 centroid conversion ----------------
// one block per class, 128 threads (thread t owns float4 at col 4t)
__global__ void k_conv() {
    __shared__ float sc_sh;
    int c = blockIdx.x, t = threadIdx.x;
    if (c == 0 && t < 2) g_loss[t] = 0.f;
    if (t < NCHUNK) {
        int v = g_hist_part[t * C + c];
#pragma unroll
        for (int off = 16; off > 0; off >>= 1) v += __shfl_down_sync(0xffffffffu, v, off);
        if (t == 0) sc_sh = TEMP_INV / (float)v;
    }
    float4 acc = make_float4(0.f, 0.f, 0.f, 0.f);
#pragma unroll 8
    for (int chunk = 0; chunk < NCHUNK; chunk++) {
        float4 v = *reinterpret_cast<const float4*>(g_part + (size_t)chunk * (C * D) + c * D + 4 * t);
        acc.x += v.x; acc.y += v.y; acc.z += v.z; acc.w += v.w;
    }
    __syncthreads();
    float sc = sc_sh;
    __half2* dsth = reinterpret_cast<__half2*>(g_cent + c * D);
    dsth[2 * t]     = __floats2half2_rn(acc.x * sc, acc.y * sc);
    dsth[2 * t + 1] = __floats2half2_rn(acc.z * sc, acc.w * sc);
}

// ---------------- K2: staging + interleaved dual GEMM + weighted CE + finalize -------
__device__ __forceinline__ uint32_t f2h2(const float* p) {
    float2 f = *reinterpret_cast<const float2*>(p);
    __half2 h = __float22half2_rn(f);
    return *reinterpret_cast<uint32_t*>(&h);
}

__device__ __forceinline__ void mma16816(float* c,
                                         uint32_t a0, uint32_t a1, uint32_t a2, uint32_t a3,
                                         uint32_t b0, uint32_t b1) {
    asm volatile(
        "mma.sync.aligned.m16n8k16.row.col.f32.f16.f16.f32 "
        "{%0,%1,%2,%3}, {%4,%5,%6,%7}, {%8,%9}, {%0,%1,%2,%3};\n"
        : "+f"(c[0]), "+f"(c[1]), "+f"(c[2]), "+f"(c[3])
        : "r"(a0), "r"(a1), "r"(a2), "r"(a3), "r"(b0), "r"(b1));
}

#define P2_THREADS 256
#define P2_BLOCKS 296
#define CENT_STRIDE_H2 260   // (512+8)/2 half2 per class row -> conflict-free B loads
#define CENT_SMEM_BYTES (C * 520 * 2)

__global__ __launch_bounds__(P2_THREADS, 2)
void k_main(const float* __restrict__ S1, const float* __restrict__ S2,
            const int* __restrict__ labels, const float* __restrict__ sim,
            float* __restrict__ out, int n) {
    extern __shared__ __half cent_sh[];
    __shared__ float red[8][2];

    int tid = threadIdx.x;

    // Stage fp16 centroids into padded shared: 4096 uint4 (8 halfs each)
    {
        const uint4* src = reinterpret_cast<const uint4*>(g_cent);
        for (int i = tid; i < C * D / 8; i += P2_THREADS) {
            int c = i >> 6;                 // 64 uint4 per class row
            int x8 = i & 63;                // which 8-half chunk
            *reinterpret_cast<uint4*>(cent_sh + c * 520 + x8 * 8) = src[i];
        }
    }
    __syncthreads();

    const __half2* centh2 = reinterpret_cast<const __half2*>(cent_sh);
    int lane = tid & 31, wid = tid >> 5;
    int g = lane >> 2, t = lane & 3;
    int gwarp = blockIdx.x * (P2_THREADS / 32) + wid;
    int nwarps = gridDim.x * (P2_THREADS / 32);
    int ntiles = n >> 4;

    float lsum0 = 0.f, lsum1 = 0.f;

    for (int tile = gwarp; tile < ntiles; tile += nwarps) {
        int rb = tile << 4;

        // Hoisted: labels + sim weights load BEFORE the MMA loop (overlap latency)
        int lab0 = labels[rb + g];
        int lab1 = labels[rb + 8 + g];
        float4 wv0 = *reinterpret_cast<const float4*>(sim + (size_t)(rb + g) * 16 + t * 4);
        float4 wv1 = *reinterpret_cast<const float4*>(sim + (size_t)(rb + 8 + g) * 16 + t * 4);

        const float* a1r1 = S1 + (size_t)(rb + g) * D;
        const float* a1r2 = a1r1 + 8 * D;
        const float* a2r1 = S2 + (size_t)(rb + g) * D;
        const float* a2r2 = a2r1 + 8 * D;

        float acc[2][8][4];
#pragma unroll
        for (int m = 0; m < 2; m++)
#pragma unroll
            for (int nt = 0; nt < 8; nt++)
#pragma unroll
                for (int j = 0; j < 4; j++) acc[m][nt][j] = 0.f;

#pragma unroll 8
        for (int kt = 0; kt < D / 16; kt++) {
            int k0 = kt * 16 + t * 2;
            uint32_t a0m0 = f2h2(a1r1 + k0);
            uint32_t a1m0 = f2h2(a1r2 + k0);
            uint32_t a2m0 = f2h2(a1r1 + k0 + 8);
            uint32_t a3m0 = f2h2(a1r2 + k0 + 8);
            uint32_t a0m1 = f2h2(a2r1 + k0);
            uint32_t a1m1 = f2h2(a2r2 + k0);
            uint32_t a2m1 = f2h2(a2r1 + k0 + 8);
            uint32_t a3m1 = f2h2(a2r2 + k0 + 8);
#pragma unroll
            for (int nt = 0; nt < 8; nt++) {
                const __half2* bp = centh2 + (nt * 8 + g) * CENT_STRIDE_H2 + (k0 >> 1);
                uint32_t b0 = *reinterpret_cast<const uint32_t*>(bp);
                uint32_t b1 = *reinterpret_cast<const uint32_t*>(bp + 4);
                mma16816(acc[0][nt], a0m0, a1m0, a2m0, a3m0, b0, b1);
                mma16816(acc[1][nt], a0m1, a1m1, a2m1, a3m1, b0, b1);
            }
        }

        float w0 = wv0.x + wv0.y + wv0.z + wv0.w;
        float w1 = wv1.x + wv1.y + wv1.z + wv1.w;
        w0 += __shfl_xor_sync(0xffffffffu, w0, 1);
        w0 += __shfl_xor_sync(0xffffffffu, w0, 2);
        w1 += __shfl_xor_sync(0xffffffffu, w1, 1);
        w1 += __shfl_xor_sync(0xffffffffu, w1, 2);
        w0 *= (1.f / 16.f);
        w1 *= (1.f / 16.f);

#pragma unroll
        for (int m = 0; m < 2; m++) {
#pragma unroll
            for (int j = 0; j < 2; j++) {
                int lab = j ? lab1 : lab0;
                float w = j ? w1 : w0;
                float mx = -1e30f;
#pragma unroll
                for (int nt = 0; nt < 8; nt++) {
                    mx = fmaxf(mx, acc[m][nt][2 * j]);
                    mx = fmaxf(mx, acc[m][nt][2 * j + 1]);
                }
                mx = fmaxf(mx, __shfl_xor_sync(0xffffffffu, mx, 1));
                mx = fmaxf(mx, __shfl_xor_sync(0xffffffffu, mx, 2));
                float s = 0.f;
#pragma unroll
                for (int nt = 0; nt < 8; nt++) {
                    s += __expf(acc[m][nt][2 * j] - mx);
                    s += __expf(acc[m][nt][2 * j + 1] - mx);
                }
                s += __shfl_xor_sync(0xffffffffu, s, 1);
                s += __shfl_xor_sync(0xffffffffu, s, 2);
                float lse = mx + __logf(s);
                int nt_l = lab >> 3;
                int t_l = (lab >> 1) & 3;
                float sel = 0.f;
#pragma unroll
                for (int nt = 0; nt < 8; nt++) {
                    float v = (lab & 1) ? acc[m][nt][2 * j + 1] : acc[m][nt][2 * j];
                    sel += ((nt == nt_l) && (t == t_l)) ? v : 0.f;
                }
                sel += __shfl_xor_sync(0xffffffffu, sel, 1);
                sel += __shfl_xor_sync(0xffffffffu, sel, 2);
                float ce = (lse - sel) * w;   // quad-uniform
                if (m == 0) lsum0 += ce;
                else        lsum1 += ce;
            }
        }
    }

    // CE accumulated on all 4 quad lanes -> scale by 1/4
    lsum0 *= 0.25f;
    lsum1 *= 0.25f;
#pragma unroll
    for (int off = 16; off > 0; off >>= 1) {
        lsum0 += __shfl_down_sync(0xffffffffu, lsum0, off);
        lsum1 += __shfl_down_sync(0xffffffffu, lsum1, off);
    }
    if (lane == 0) { red[wid][0] = lsum0; red[wid][1] = lsum1; }
    __syncthreads();
    if (tid == 0) {
        float s0 = 0.f, s1 = 0.f;
#pragma unroll
        for (int wq = 0; wq < P2_THREADS / 32; wq++) { s0 += red[wq][0]; s1 += red[wq][1]; }
        atomicAdd(&g_loss[0], s0);
        atomicAdd(&g_loss[1], s1);
        __threadfence();
        int ticket = atomicAdd(&g_done, 1);
        if (ticket == gridDim.x - 1) {
            float L = g_loss[0] / (float)n;
            float G = g_loss[1] / (float)n;
            out[0] = 0.5f * ((1.f - GLW) * L + GLW * G);
            atomicExch(&g_done, 0);   // reset for next graph replay
        }
    }
}

// ---------------- launch ----------------
extern "C" void kernel_launch(void* const* d_in, const int* in_sizes, int n_in,
                              void* d_out, int out_size) {
    const float* S1 = (const float*)d_in[0];
    const float* S2 = (const float*)d_in[1];
    const int* seg = (const int*)d_in[2];
    const float* sim = (const float*)d_in[3];
    int n = in_sizes[2];  // N = 65536

    cudaFuncSetAttribute(k_csum, cudaFuncAttributeMaxDynamicSharedMemorySize,
                         16 * C * P1_COLS * (int)sizeof(float));
    cudaFuncSetAttribute(k_main, cudaFuncAttributeMaxDynamicSharedMemorySize,
                         CENT_SMEM_BYTES);

    k_csum<<<16 * NCHUNK, P1_THREADS, 16 * C * P1_COLS * sizeof(float)>>>(S1, seg, n);
    k_conv<<<C, 128>>>();
    k_main<<<P2_BLOCKS, P2_THREADS, CENT_SMEM_BYTES>>>(S1, S2, seg, sim, (float*)d_out, n);
}

// round 8
// speedup vs baseline: 1.4729x; 1.2554x over previous
#include <cuda_runtime.h>
#include <cuda_fp16.h>
#include <cstdint>

#define C 64
#define D 512
#define TEMP_INV 10.0f
#define GLW 0.5f
#define NHB 128            // histogram/scatter blocks
#define NSEG 8             // segments per class in gather

// ---------------- device globals (scratch; no allocation allowed) ----------------
__device__ int    g_hist_part[NHB * C];     // per-block label histograms
__device__ int    g_base[NHB * C];          // per-block scatter bases
__device__ int    g_count[C];
__device__ int    g_off[C];
__device__ float  g_scale[C];               // TEMP_INV / count
__device__ int    g_rows[65536];            // row indices sorted by label
__device__ float  g_part[C * NSEG * D];     // per-(class,seg) partial sums (overwritten)
__device__ __half g_cent[C * D];            // fp16 centroids, TEMP/count folded
__device__ float  g_loss[2];
__device__ int    g_done;                   // zero-init at load; reset each run

// ---------------- K0: per-block label histogram ----------------
__global__ void k_hist(const int* __restrict__ labels, int n) {
    __shared__ int h[C];
    int b = blockIdx.x, t = threadIdx.x;
    if (t < C) h[t] = 0;
    __syncthreads();
    int per = n / NHB;                       // 512
    for (int i = t; i < per; i += blockDim.x)
        atomicAdd(&h[labels[b * per + i]], 1);
    __syncthreads();
    if (t < C) g_hist_part[b * C + t] = h[t];
}

// ---------------- K1: counts, offsets, per-block bases, scales (1 block) ----------------
__global__ void k_scan() {
    __shared__ int cnt_sh[C];
    int c = threadIdx.x;                     // 64 threads
    int total = 0;
#pragma unroll 8
    for (int b = 0; b < NHB; b++) total += g_hist_part[b * C + c];
    cnt_sh[c] = total;
    __syncthreads();
    int off = 0;
    for (int i = 0; i < c; i++) off += cnt_sh[i];
    g_count[c] = total;
    g_off[c] = off;
    g_scale[c] = TEMP_INV / (float)total;
    int running = off;
    for (int b = 0; b < NHB; b++) {
        g_base[b * C + c] = running;
        running += g_hist_part[b * C + c];
    }
    if (c < 2) g_loss[c] = 0.f;
}

// ---------------- K2: scatter row indices into label-sorted order ----------------
__global__ void k_scatter(const int* __restrict__ labels, int n) {
    __shared__ int cur[C];
    int b = blockIdx.x, t = threadIdx.x;
    if (t < C) cur[t] = g_base[b * C + t];
    __syncthreads();
    int per = n / NHB;                       // 512
    for (int i = t; i < per; i += blockDim.x) {
        int row = b * per + i;
        int lab = labels[row];
        int pos = atomicAdd(&cur[lab], 1);
        g_rows[pos] = row;
    }
}

// ---------------- K3: register-accumulation gather (no smem scatter) ----------------
// grid = C*NSEG = 512 blocks, 512 threads; thread t owns column t; ~4 CTAs/SM.
__global__ __launch_bounds__(512)
void k_gather(const float* __restrict__ S1) {
    int c = blockIdx.x >> 3, seg = blockIdx.x & (NSEG - 1);
    int cnt = g_count[c], off = g_off[c];
    int s0 = off + (cnt * seg) / NSEG;
    int s1 = off + (cnt * (seg + 1)) / NSEG;
    int t = threadIdx.x;
    float acc = 0.f;
    int i = s0;
    for (; i + 8 <= s1; i += 8) {
        // front-batched independent loads (row idx broadcast, values coalesced)
        int r0 = g_rows[i + 0], r1 = g_rows[i + 1], r2 = g_rows[i + 2], r3 = g_rows[i + 3];
        int r4 = g_rows[i + 4], r5 = g_rows[i + 5], r6 = g_rows[i + 6], r7 = g_rows[i + 7];
        float v0 = S1[(size_t)r0 * D + t];
        float v1 = S1[(size_t)r1 * D + t];
        float v2 = S1[(size_t)r2 * D + t];
        float v3 = S1[(size_t)r3 * D + t];
        float v4 = S1[(size_t)r4 * D + t];
        float v5 = S1[(size_t)r5 * D + t];
        float v6 = S1[(size_t)r6 * D + t];
        float v7 = S1[(size_t)r7 * D + t];
        acc += v0; acc += v1; acc += v2; acc += v3;
        acc += v4; acc += v5; acc += v6; acc += v7;
    }
    for (; i < s1; i++) acc += S1[(size_t)g_rows[i] * D + t];
    g_part[blockIdx.x * D + t] = acc;
}

// ---------------- K4: reduce segment partials -> fp16 centroids ----------------
__global__ void k_conv() {
    int c = blockIdx.x, t = threadIdx.x;     // 64 blocks x 512 threads
    float s = 0.f;
#pragma unroll
    for (int seg = 0; seg < NSEG; seg++) s += g_part[(c * NSEG + seg) * D + t];
    g_cent[c * D + t] = __float2half(s * g_scale[c]);
}

// ---------------- K5: staging + interleaved dual GEMM + weighted CE + finalize -------
__device__ __forceinline__ uint32_t f2h2(const float* p) {
    float2 f = *reinterpret_cast<const float2*>(p);
    __half2 h = __float22half2_rn(f);
    return *reinterpret_cast<uint32_t*>(&h);
}

__device__ __forceinline__ void mma16816(float* c,
                                         uint32_t a0, uint32_t a1, uint32_t a2, uint32_t a3,
                                         uint32_t b0, uint32_t b1) {
    asm volatile(
        "mma.sync.aligned.m16n8k16.row.col.f32.f16.f16.f32 "
        "{%0,%1,%2,%3}, {%4,%5,%6,%7}, {%8,%9}, {%0,%1,%2,%3};\n"
        : "+f"(c[0]), "+f"(c[1]), "+f"(c[2]), "+f"(c[3])
        : "r"(a0), "r"(a1), "r"(a2), "r"(a3), "r"(b0), "r"(b1));
}

#define P2_THREADS 256
#define P2_BLOCKS 296
#define CENT_STRIDE_H2 260   // (512+8)/2 half2 per class row -> conflict-free B loads
#define CENT_SMEM_BYTES (C * 520 * 2)

__global__ __launch_bounds__(P2_THREADS, 2)
void k_main(const float* __restrict__ S1, const float* __restrict__ S2,
            const int* __restrict__ labels, const float* __restrict__ sim,
            float* __restrict__ out, int n) {
    extern __shared__ __half cent_sh[];
    __shared__ float red[8][2];

    int tid = threadIdx.x;

    // Stage fp16 centroids into padded shared: 4096 uint4 (8 halfs each)
    {
        const uint4* src = reinterpret_cast<const uint4*>(g_cent);
        for (int i = tid; i < C * D / 8; i += P2_THREADS) {
            int c = i >> 6;                 // 64 uint4 per class row
            int x8 = i & 63;                // which 8-half chunk
            *reinterpret_cast<uint4*>(cent_sh + c * 520 + x8 * 8) = src[i];
        }
    }
    __syncthreads();

    const __half2* centh2 = reinterpret_cast<const __half2*>(cent_sh);
    int lane = tid & 31, wid = tid >> 5;
    int g = lane >> 2, t = lane & 3;
    int gwarp = blockIdx.x * (P2_THREADS / 32) + wid;
    int nwarps = gridDim.x * (P2_THREADS / 32);
    int ntiles = n >> 4;

    float lsum0 = 0.f, lsum1 = 0.f;

    for (int tile = gwarp; tile < ntiles; tile += nwarps) {
        int rb = tile << 4;

        // Hoisted: labels + sim weights load BEFORE the MMA loop (overlap latency)
        int lab0 = labels[rb + g];
        int lab1 = labels[rb + 8 + g];
        float4 wv0 = *reinterpret_cast<const float4*>(sim + (size_t)(rb + g) * 16 + t * 4);
        float4 wv1 = *reinterpret_cast<const float4*>(sim + (size_t)(rb + 8 + g) * 16 + t * 4);

        const float* a1r1 = S1 + (size_t)(rb + g) * D;
        const float* a1r2 = a1r1 + 8 * D;
        const float* a2r1 = S2 + (size_t)(rb + g) * D;
        const float* a2r2 = a2r1 + 8 * D;

        float acc[2][8][4];
#pragma unroll
        for (int m = 0; m < 2; m++)
#pragma unroll
            for (int nt = 0; nt < 8; nt++)
#pragma unroll
                for (int j = 0; j < 4; j++) acc[m][nt][j] = 0.f;

#pragma unroll 8
        for (int kt = 0; kt < D / 16; kt++) {
            int k0 = kt * 16 + t * 2;
            uint32_t a0m0 = f2h2(a1r1 + k0);
            uint32_t a1m0 = f2h2(a1r2 + k0);
            uint32_t a2m0 = f2h2(a1r1 + k0 + 8);
            uint32_t a3m0 = f2h2(a1r2 + k0 + 8);
            uint32_t a0m1 = f2h2(a2r1 + k0);
            uint32_t a1m1 = f2h2(a2r2 + k0);
            uint32_t a2m1 = f2h2(a2r1 + k0 + 8);
            uint32_t a3m1 = f2h2(a2r2 + k0 + 8);
#pragma unroll
            for (int nt = 0; nt < 8; nt++) {
                const __half2* bp = centh2 + (nt * 8 + g) * CENT_STRIDE_H2 + (k0 >> 1);
                uint32_t b0 = *reinterpret_cast<const uint32_t*>(bp);
                uint32_t b1 = *reinterpret_cast<const uint32_t*>(bp + 4);
                mma16816(acc[0][nt], a0m0, a1m0, a2m0, a3m0, b0, b1);
                mma16816(acc[1][nt], a0m1, a1m1, a2m1, a3m1, b0, b1);
            }
        }

        float w0 = wv0.x + wv0.y + wv0.z + wv0.w;
        float w1 = wv1.x + wv1.y + wv1.z + wv1.w;
        w0 += __shfl_xor_sync(0xffffffffu, w0, 1);
        w0 += __shfl_xor_sync(0xffffffffu, w0, 2);
        w1 += __shfl_xor_sync(0xffffffffu, w1, 1);
        w1 += __shfl_xor_sync(0xffffffffu, w1, 2);
        w0 *= (1.f / 16.f);
        w1 *= (1.f / 16.f);

#pragma unroll
        for (int m = 0; m < 2; m++) {
#pragma unroll
            for (int j = 0; j < 2; j++) {
                int lab = j ? lab1 : lab0;
                float w = j ? w1 : w0;
                float mx = -1e30f;
#pragma unroll
                for (int nt = 0; nt < 8; nt++) {
                    mx = fmaxf(mx, acc[m][nt][2 * j]);
                    mx = fmaxf(mx, acc[m][nt][2 * j + 1]);
                }
                mx = fmaxf(mx, __shfl_xor_sync(0xffffffffu, mx, 1));
                mx = fmaxf(mx, __shfl_xor_sync(0xffffffffu, mx, 2));
                float s = 0.f;
#pragma unroll
                for (int nt = 0; nt < 8; nt++) {
                    s += __expf(acc[m][nt][2 * j] - mx);
                    s += __expf(acc[m][nt][2 * j + 1] - mx);
                }
                s += __shfl_xor_sync(0xffffffffu, s, 1);
                s += __shfl_xor_sync(0xffffffffu, s, 2);
                float lse = mx + __logf(s);
                int nt_l = lab >> 3;
                int t_l = (lab >> 1) & 3;
                float sel = 0.f;
#pragma unroll
                for (int nt = 0; nt < 8; nt++) {
                    float v = (lab & 1) ? acc[m][nt][2 * j + 1] : acc[m][nt][2 * j];
                    sel += ((nt == nt_l) && (t == t_l)) ? v : 0.f;
                }
                sel += __shfl_xor_sync(0xffffffffu, sel, 1);
                sel += __shfl_xor_sync(0xffffffffu, sel, 2);
                float ce = (lse - sel) * w;   // quad-uniform
                if (m == 0) lsum0 += ce;
                else        lsum1 += ce;
            }
        }
    }

    // CE accumulated on all 4 quad lanes -> scale by 1/4
    lsum0 *= 0.25f;
    lsum1 *= 0.25f;
#pragma unroll
    for (int off = 16; off > 0; off >>= 1) {
        lsum0 += __shfl_down_sync(0xffffffffu, lsum0, off);
        lsum1 += __shfl_down_sync(0xffffffffu, lsum1, off);
    }
    if (lane == 0) { red[wid][0] = lsum0; red[wid][1] = lsum1; }
    __syncthreads();
    if (tid == 0) {
        float s0 = 0.f, s1 = 0.f;
#pragma unroll
        for (int wq = 0; wq < P2_THREADS / 32; wq++) { s0 += red[wq][0]; s1 += red[wq][1]; }
        atomicAdd(&g_loss[0], s0);
        atomicAdd(&g_loss[1], s1);
        __threadfence();
        int ticket = atomicAdd(&g_done, 1);
        if (ticket == gridDim.x - 1) {
            float L = g_loss[0] / (float)n;
            float G = g_loss[1] / (float)n;
            out[0] = 0.5f * ((1.f - GLW) * L + GLW * G);
            atomicExch(&g_done, 0);   // reset for next graph replay
        }
    }
}

// ---------------- launch ----------------
extern "C" void kernel_launch(void* const* d_in, const int* in_sizes, int n_in,
                              void* d_out, int out_size) {
    const float* S1 = (const float*)d_in[0];
    const float* S2 = (const float*)d_in[1];
    const int* seg = (const int*)d_in[2];
    const float* sim = (const float*)d_in[3];
    int n = in_sizes[2];  // N = 65536

    cudaFuncSetAttribute(k_main, cudaFuncAttributeMaxDynamicSharedMemorySize,
                         CENT_SMEM_BYTES);

    k_hist<<<NHB, 256>>>(seg, n);
    k_scan<<<1, C>>>();
    k_scatter<<<NHB, 256>>>(seg, n);
    k_gather<<<C * NSEG, 512>>>(S1);
    k_conv<<<C, 512>>>();
    k_main<<<P2_BLOCKS, P2_THREADS, CENT_SMEM_BYTES>>>(S1, S2, seg, sim, (float*)d_out, n);
}